// round 16
// baseline (speedup 1.0000x reference)
#include <cuda_runtime.h>
#include <cuda_fp16.h>
#include <cstdint>

#define N_ACT   1500000
#define ROWS_PB 256                                 // 8 warps x 32 rows
#define NBC     ((N_ACT + ROWS_PB - 1) / ROWS_PB)   // 5860 blocks
#define NB_CVT  ((N_ACT * 32 / 8 + 255) / 256)
#define NB_FIN  ((N_ACT * 32 / 8 + 255) / 256)      // 8 halfs per thread
#define BN_EPS  1e-5f

// ---------------- scratch (no allocations allowed) ----------------
__device__ __align__(16) __half g_x16[(size_t)N_ACT * 32];  // fp16 copy of x
__device__ __align__(16) __half g_h1h[(size_t)N_ACT * 32];  // conv1 out (fp16)
__device__ __align__(16) __half g_h2h[(size_t)N_ACT * 32];  // conv2 out (fp16)
__device__ __align__(16) __half g_zero[32];                 // zero pad (conv1)
__device__ __align__(16) __half g_pad[32];                  // -d pad (conv2)
__device__ uint2  g_Wf[2][2048];               // fp16 B frags: [k][s*4+t][lane]
__device__ float  g_part1[64 * NBC];           // transposed: [stat][block]
__device__ float  g_part2[64 * NBC];
__device__ float  g_coef1[64], g_coef2[64];    // [a(32), c(32)] : y = a*h + c

__device__ __forceinline__ uint32_t smem_u32(const void* p) {
    uint32_t a;
    asm("{ .reg .u64 t; cvta.to.shared.u64 t, %1; cvt.u32.u64 %0, t; }" : "=r"(a) : "l"(p));
    return a;
}
__device__ __forceinline__ uint32_t h2pack(float lo, float hi) {
    __half2 p = __floats2half2_rn(lo, hi);
    return *reinterpret_cast<uint32_t*>(&p);
}
__device__ __forceinline__ void mma_f16(float* d, const uint32_t* a, uint2 b) {
    asm volatile(
        "mma.sync.aligned.m16n8k16.row.col.f32.f16.f16.f32 "
        "{%0,%1,%2,%3}, {%4,%5,%6,%7}, {%8,%9}, {%0,%1,%2,%3};"
        : "+f"(d[0]), "+f"(d[1]), "+f"(d[2]), "+f"(d[3])
        : "r"(a[0]), "r"(a[1]), "r"(a[2]), "r"(a[3]), "r"(b.x), "r"(b.y));
}
__device__ __forceinline__ void ldmx4(uint32_t* a, uint32_t addr) {
    asm volatile("ldmatrix.sync.aligned.m8n8.x4.shared.b16 {%0,%1,%2,%3}, [%4];"
        : "=r"(a[0]), "=r"(a[1]), "=r"(a[2]), "=r"(a[3]) : "r"(addr));
}
__device__ __forceinline__ uint32_t addrelu_u32(uint32_t v, __half2 d) {
    __half2 h = __hmax2(__hadd2(*(__half2*)&v, d), __floats2half2_rn(0.f, 0.f));
    return *(uint32_t*)&h;
}

// ---------------- x -> fp16 copy (8 floats per thread) ----------------
__global__ void x_to_h(const float* __restrict__ X)
{
    size_t i = (size_t)blockIdx.x * 256 + threadIdx.x;
    if (i >= (size_t)N_ACT * 32 / 8) return;
    const float4* X4 = (const float4*)X;
    float4 a = X4[2 * i], b = X4[2 * i + 1];
    uint4 o;
    o.x = h2pack(a.x, a.y); o.y = h2pack(a.z, a.w);
    o.z = h2pack(b.x, b.y); o.w = h2pack(b.z, b.w);
    ((uint4*)g_x16)[i] = o;
}

// ---- W prep: W[k][cin][cout] -> fp16 B frags; which==1 folds a1[cin] scale ----
__global__ void prep_w(const float* __restrict__ W, int which)
{
    int k = blockIdx.x, tt = threadIdx.x;        // 8 blocks x 256 threads
    int lane = tt & 31, st = tt >> 5;            // st = s*4 + t
    int g = lane >> 2, tig = lane & 3;
    int cin0 = (st >> 2) * 16 + 2 * tig;
    int cout = (st & 3) * 8 + g;
    const float* wk = W + k * 1024;
    float s00 = 1.f, s01 = 1.f, s10 = 1.f, s11 = 1.f;
    if (which) {
        s00 = g_coef1[cin0];     s01 = g_coef1[cin0 + 1];
        s10 = g_coef1[cin0 + 8]; s11 = g_coef1[cin0 + 9];
    }
    uint2 v;
    v.x = h2pack(wk[cin0 * 32 + cout] * s00,       wk[(cin0 + 1) * 32 + cout] * s01);
    v.y = h2pack(wk[(cin0 + 8) * 32 + cout] * s10, wk[(cin0 + 9) * 32 + cout] * s11);
    g_Wf[which][k * 256 + st * 32 + lane] = v;
}

// ================== conv: 32 rows/warp, triple-buffered cp.async gather ======
// A tile/warp: 32 rows x 16 words, chunk-XOR swizzle (invariant under +16 rows).
// Gathers issued 2 k-iterations ahead; wait_group 2 keeps 2 groups in flight.
// WHICH==0: src x16, pad=zeros, no transform. WHICH==1: src raw h1, pad=-d,
// post-ldmatrix transform relu(h+d) with a1 folded into W2 fragments.
template<int WHICH>
__global__ __launch_bounds__(256, 3) void conv_mma(const int* __restrict__ IDX)
{
    const __half* SRC  = WHICH ? g_h1h   : g_x16;
    __half*       DST  = WHICH ? g_h2h   : g_h1h;
    float*        part = WHICH ? g_part2 : g_part1;

    __shared__ uint32_t sA[3][8][512];           // 48 KB
    __shared__ float red[2][8][32];              //  2 KB

    const int tid   = threadIdx.x;
    const int warp  = tid >> 5;
    const int lane  = tid & 31;
    const int g     = lane >> 2;
    const int tig   = lane & 3;
    const int wrow  = warp * 32;
    const int base  = blockIdx.x * ROWS_PB;
    const int q4    = lane & 3;
    const int rsub8 = lane >> 2;                 // rows rsub8 + 8i, i=0..3

    const __half* PADp = (WHICH ? g_pad : g_zero) + q4 * 8;

    // d coefs for the fragment transform (WHICH==1 only)
    __half2 dd[2][2];
    if (WHICH) {
#pragma unroll
        for (int s = 0; s < 2; s++)
#pragma unroll
            for (int p = 0; p < 2; p++) {
                int cin = 16 * s + 8 * p + 2 * tig;
                float a0 = g_coef1[cin],      a1 = g_coef1[cin + 1];
                float c0 = g_coef1[32 + cin], c1 = g_coef1[32 + cin + 1];
                dd[s][p] = __floats2half2_rn(c0 / a0, c1 / a1);
            }
    }

    float acc[8][4];                             // [h*4+t][i]
#pragma unroll
    for (int t = 0; t < 8; t++)
#pragma unroll
        for (int i = 0; i < 4; i++) acc[t][i] = 0.f;

    const int rowc = min(base + wrow + lane, N_ACT - 1);

    // ldmatrix per-thread word offsets (rows 0-15; +256 words for rows 16-31)
    const int mat = lane >> 3;
    const int rr  = (lane & 7) + ((mat & 1) << 3);
    const int swz = (rr >> 1) & 3;
    const uint32_t w_s0 = rr * 16 + (((mat >> 1)       ^ swz) << 2);
    const uint32_t w_s1 = rr * 16 + (((2 + (mat >> 1)) ^ swz) << 2);
    const uint32_t ub[3] = { smem_u32(&sA[0][warp][0]),
                             smem_u32(&sA[1][warp][0]),
                             smem_u32(&sA[2][warp][0]) };

#define LOADA(MYJ, BUF)                                                     \
    {                                                                       \
        _Pragma("unroll")                                                   \
        for (int i = 0; i < 4; i++) {                                       \
            int j = __shfl_sync(0xffffffffu, (MYJ), rsub8 + 8 * i);         \
            const __half* src = (j < N_ACT)                                 \
                ? SRC + (size_t)j * 32 + q4 * 8 : PADp;                     \
            int r = rsub8 + 8 * i;                                          \
            uint32_t dst = (BUF) + (r * 16 + ((q4 ^ ((r >> 1) & 3)) << 2)) * 4; \
            asm volatile("cp.async.cg.shared.global [%0], [%1], 16;"        \
                         :: "r"(dst), "l"(src));                            \
        }                                                                   \
        asm volatile("cp.async.commit_group;");                             \
    }
#define COMPK(BUF, K)                                                       \
    {                                                                       \
        _Pragma("unroll")                                                   \
        for (int s = 0; s < 2; s++) {                                       \
            const uint2* wp = &g_Wf[WHICH][(K) * 256 + s * 128 + lane];     \
            uint2 w0 = wp[0], w1 = wp[32], w2 = wp[64], w3 = wp[96];        \
            _Pragma("unroll")                                               \
            for (int h = 0; h < 2; h++) {                                   \
                uint32_t afr[4];                                            \
                ldmx4(afr, (BUF) + h * 1024 + (s ? w_s1 : w_s0) * 4);       \
                if (WHICH) {                                                \
                    afr[0] = addrelu_u32(afr[0], dd[s][0]);                 \
                    afr[1] = addrelu_u32(afr[1], dd[s][0]);                 \
                    afr[2] = addrelu_u32(afr[2], dd[s][1]);                 \
                    afr[3] = addrelu_u32(afr[3], dd[s][1]);                 \
                }                                                           \
                mma_f16(acc[h * 4 + 0], afr, w0);                           \
                mma_f16(acc[h * 4 + 1], afr, w1);                           \
                mma_f16(acc[h * 4 + 2], afr, w2);                           \
                mma_f16(acc[h * 4 + 3], afr, w3);                           \
            }                                                               \
        }                                                                   \
    }

    // prologue: k=0 and k=1 gathers in flight
    int myj = IDX[rowc];
    LOADA(myj, ub[0]);
    myj = IDX[(size_t)N_ACT + rowc];
    LOADA(myj, ub[1]);
    int myj_nxt = IDX[(size_t)2 * N_ACT + rowc];     // idx for k=2

#pragma unroll 1
    for (int k = 0; k < 8; k++) {
        if (k < 6) {
            int m = myj_nxt;
            if (k < 5) myj_nxt = IDX[(size_t)(k + 3) * N_ACT + rowc];
            LOADA(m, ub[(k + 2) % 3]);               // gather k+2
            asm volatile("cp.async.wait_group 2;");  // k complete; k+1,k+2 fly
        } else if (k == 6) {
            asm volatile("cp.async.wait_group 1;");
        } else {
            asm volatile("cp.async.wait_group 0;");
        }
        __syncwarp();
        COMPK(ub[k % 3], k);
    }
#undef LOADA
#undef COMPK

    // ---- epilogue: fp16 H store + fp32 BN partials ----
    float s0[4], s1[4], q0[4], q1[4];
#pragma unroll
    for (int t = 0; t < 4; t++) { s0[t] = s1[t] = q0[t] = q1[t] = 0.f; }
#pragma unroll
    for (int h = 0; h < 2; h++) {
        const int r0 = base + wrow + 16 * h + g, r1 = r0 + 8;
        const bool v0 = r0 < N_ACT, v1 = r1 < N_ACT;
#pragma unroll
        for (int t = 0; t < 4; t++) {
            float c0 = acc[h*4+t][0], c1 = acc[h*4+t][1];
            float c2 = acc[h*4+t][2], c3 = acc[h*4+t][3];
            int col = t * 8 + tig * 2;
            if (v0) *(__half2*)(DST + (size_t)r0 * 32 + col) = __floats2half2_rn(c0, c1);
            if (v1) *(__half2*)(DST + (size_t)r1 * 32 + col) = __floats2half2_rn(c2, c3);
            s0[t] += (v0 ? c0 : 0.f) + (v1 ? c2 : 0.f);
            q0[t] += (v0 ? c0 * c0 : 0.f) + (v1 ? c2 * c2 : 0.f);
            s1[t] += (v0 ? c1 : 0.f) + (v1 ? c3 : 0.f);
            q1[t] += (v0 ? c1 * c1 : 0.f) + (v1 ? c3 * c3 : 0.f);
        }
    }
#pragma unroll
    for (int off = 4; off <= 16; off <<= 1) {
#pragma unroll
        for (int t = 0; t < 4; t++) {
            s0[t] += __shfl_xor_sync(0xffffffffu, s0[t], off);
            q0[t] += __shfl_xor_sync(0xffffffffu, q0[t], off);
            s1[t] += __shfl_xor_sync(0xffffffffu, s1[t], off);
            q1[t] += __shfl_xor_sync(0xffffffffu, q1[t], off);
        }
    }
    if (lane < 4) {
#pragma unroll
        for (int t = 0; t < 4; t++) {
            red[0][warp][t * 8 + lane * 2]     = s0[t];
            red[0][warp][t * 8 + lane * 2 + 1] = s1[t];
            red[1][warp][t * 8 + lane * 2]     = q0[t];
            red[1][warp][t * 8 + lane * 2 + 1] = q1[t];
        }
    }
    __syncthreads();
    if (warp == 0) {
        float ts = 0.f, tq = 0.f;
#pragma unroll
        for (int w = 0; w < 8; w++) { ts += red[0][w][lane]; tq += red[1][w][lane]; }
        part[(size_t)lane        * NBC + blockIdx.x] = ts;
        part[(size_t)(32 + lane) * NBC + blockIdx.x] = tq;
    }
}

// ---- reduce + coef fused: 32 blocks; which==0 also writes the conv2 pad row ----
__global__ void reduce_coef(const float* __restrict__ gamma,
                            const float* __restrict__ beta, int which)
{
    const float* part = which ? g_part2 : g_part1;
    float*       coef = which ? g_coef2 : g_coef1;
    const int c = blockIdx.x;
    const float* rs = part + (size_t)c        * NBC;
    const float* rq = part + (size_t)(32 + c) * NBC;
    float s = 0.f, q = 0.f;
#pragma unroll 4
    for (int i = threadIdx.x; i < NBC; i += 256) { s += rs[i]; q += rq[i]; }
    __shared__ float shs[256], shq[256];
    shs[threadIdx.x] = s;
    shq[threadIdx.x] = q;
    __syncthreads();
#pragma unroll
    for (int o = 128; o > 0; o >>= 1) {
        if (threadIdx.x < o) {
            shs[threadIdx.x] += shs[threadIdx.x + o];
            shq[threadIdx.x] += shq[threadIdx.x + o];
        }
        __syncthreads();
    }
    if (threadIdx.x == 0) {
        float mean = shs[0] / (float)N_ACT;
        float var  = fmaxf(shq[0] / (float)N_ACT - mean * mean, 0.f);
        float a    = gamma[c] * rsqrtf(var + BN_EPS);
        float cc   = beta[c] - mean * a;
        coef[c]      = a;
        coef[32 + c] = cc;
        if (which == 0) g_pad[c] = __float2half(-cc / a);  // relu(pad+d) == 0
    }
}

// ------------- bn2 + residual add -> out (8 halfs per thread) -------------
__global__ void final_kernel(const float* __restrict__ X, float* __restrict__ O)
{
    size_t i8 = (size_t)blockIdx.x * 256 + threadIdx.x;
    if (i8 >= (size_t)N_ACT * 32 / 8) return;
    int cb = (int)(i8 & 3);                     // channel base = cb*8
    float4 a0 = ((const float4*)g_coef2)[cb * 2];
    float4 a1 = ((const float4*)g_coef2)[cb * 2 + 1];
    float4 c0 = ((const float4*)g_coef2)[8 + cb * 2];
    float4 c1 = ((const float4*)g_coef2)[8 + cb * 2 + 1];
    uint4 hv = ((const uint4*)g_h2h)[i8];
    float2 v0 = __half22float2(*(__half2*)&hv.x);
    float2 v1 = __half22float2(*(__half2*)&hv.y);
    float2 v2 = __half22float2(*(__half2*)&hv.z);
    float2 v3 = __half22float2(*(__half2*)&hv.w);
    float4 x0 = ((const float4*)X)[2 * i8], x1 = ((const float4*)X)[2 * i8 + 1];
    float4 o0, o1;
    o0.x = fmaf(v0.x, a0.x, c0.x) + x0.x;
    o0.y = fmaf(v0.y, a0.y, c0.y) + x0.y;
    o0.z = fmaf(v1.x, a0.z, c0.z) + x0.z;
    o0.w = fmaf(v1.y, a0.w, c0.w) + x0.w;
    o1.x = fmaf(v2.x, a1.x, c1.x) + x1.x;
    o1.y = fmaf(v2.y, a1.y, c1.y) + x1.y;
    o1.z = fmaf(v3.x, a1.z, c1.z) + x1.z;
    o1.w = fmaf(v3.y, a1.w, c1.w) + x1.w;
    ((float4*)O)[2 * i8]     = o0;
    ((float4*)O)[2 * i8 + 1] = o1;
}

extern "C" void kernel_launch(void* const* d_in, const int* in_sizes, int n_in,
                              void* d_out, int out_size)
{
    const float* x   = (const float*)d_in[0];
    const int*   idx = (const int*)  d_in[1];
    const float* W1  = (const float*)d_in[2];
    const float* g1  = (const float*)d_in[3];
    const float* b1  = (const float*)d_in[4];
    const float* W2  = (const float*)d_in[5];
    const float* g2  = (const float*)d_in[6];
    const float* b2  = (const float*)d_in[7];
    float* out = (float*)d_out;

    x_to_h <<<NB_CVT, 256>>>(x);              // x16 = fp16(x)
    prep_w <<<8, 256>>>(W1, 0);
    conv_mma<0><<<NBC, 256>>>(idx);           // h1 = conv1(x16), partials1
    reduce_coef<<<32, 256>>>(g1, b1, 0);      // coef1 + pad row
    prep_w <<<8, 256>>>(W2, 1);               // W2' = a1-scaled fragments
    conv_mma<1><<<NBC, 256>>>(idx);           // h2 = conv2(relu(h1+d))*a1-fold
    reduce_coef<<<32, 256>>>(g2, b2, 1);      // coef2
    final_kernel<<<NB_FIN, 256>>>(x, out);    // out = bn2(h2) + x
}

// round 17
// speedup vs baseline: 1.0843x; 1.0843x over previous
#include <cuda_runtime.h>
#include <cuda_fp16.h>
#include <cstdint>

#define N_ACT   1500000
#define ROWS_PB 256                                 // 8 warps x 32 rows
#define NBC     ((N_ACT + ROWS_PB - 1) / ROWS_PB)   // 5860 blocks
#define NB_CVT  ((N_ACT * 32 / 8 + 255) / 256)
#define NB_FIN  ((N_ACT * 32 / 8 + 255) / 256)      // 8 halfs per thread
#define BN_EPS  1e-5f

// ---------------- scratch (no allocations allowed) ----------------
__device__ __align__(16) __half g_x16[(size_t)N_ACT * 32];  // fp16 copy of x
__device__ __align__(16) __half g_h1h[(size_t)N_ACT * 32];  // conv1 out (fp16)
__device__ __align__(16) __half g_h2h[(size_t)N_ACT * 32];  // conv2 out (fp16)
__device__ __align__(16) __half g_zero[32];                 // zero pad (conv1)
__device__ __align__(16) __half g_pad[32];                  // -d pad (conv2)
__device__ uint2  g_Wf[2][2048];               // fp16 B frags: [k][s*4+t][lane]
__device__ float  g_stat[2][64];               // atomically accumulated [sum|sumsq]
__device__ float  g_coef1[64], g_coef2[64];    // [a(32), c(32)] : y = a*h + c

__device__ __forceinline__ uint32_t smem_u32(const void* p) {
    uint32_t a;
    asm("{ .reg .u64 t; cvta.to.shared.u64 t, %1; cvt.u32.u64 %0, t; }" : "=r"(a) : "l"(p));
    return a;
}
__device__ __forceinline__ uint32_t h2pack(float lo, float hi) {
    __half2 p = __floats2half2_rn(lo, hi);
    return *reinterpret_cast<uint32_t*>(&p);
}
__device__ __forceinline__ void mma_f16(float* d, const uint32_t* a, uint2 b) {
    asm volatile(
        "mma.sync.aligned.m16n8k16.row.col.f32.f16.f16.f32 "
        "{%0,%1,%2,%3}, {%4,%5,%6,%7}, {%8,%9}, {%0,%1,%2,%3};"
        : "+f"(d[0]), "+f"(d[1]), "+f"(d[2]), "+f"(d[3])
        : "r"(a[0]), "r"(a[1]), "r"(a[2]), "r"(a[3]), "r"(b.x), "r"(b.y));
}
__device__ __forceinline__ void ldmx4(uint32_t* a, uint32_t addr) {
    asm volatile("ldmatrix.sync.aligned.m8n8.x4.shared.b16 {%0,%1,%2,%3}, [%4];"
        : "=r"(a[0]), "=r"(a[1]), "=r"(a[2]), "=r"(a[3]) : "r"(addr));
}
__device__ __forceinline__ uint32_t addrelu_u32(uint32_t v, __half2 d) {
    __half2 h = __hmax2(__hadd2(*(__half2*)&v, d), __floats2half2_rn(0.f, 0.f));
    return *(uint32_t*)&h;
}

// ---------------- x -> fp16 copy (8 floats per thread) ----------------
__global__ void x_to_h(const float* __restrict__ X)
{
    size_t i = (size_t)blockIdx.x * 256 + threadIdx.x;
    if (i >= (size_t)N_ACT * 32 / 8) return;
    const float4* X4 = (const float4*)X;
    float4 a = X4[2 * i], b = X4[2 * i + 1];
    uint4 o;
    o.x = h2pack(a.x, a.y); o.y = h2pack(a.z, a.w);
    o.z = h2pack(b.x, b.y); o.w = h2pack(b.z, b.w);
    ((uint4*)g_x16)[i] = o;
}

// ---- W prep: fp16 B frags (which==1 folds a1[cin]); zeroes g_stat[which] ----
__global__ void prep_w(const float* __restrict__ W, int which)
{
    int k = blockIdx.x, tt = threadIdx.x;        // 8 blocks x 256 threads
    if (k == 0 && tt < 64) g_stat[which][tt] = 0.f;   // ordered before conv
    int lane = tt & 31, st = tt >> 5;            // st = s*4 + t
    int g = lane >> 2, tig = lane & 3;
    int cin0 = (st >> 2) * 16 + 2 * tig;
    int cout = (st & 3) * 8 + g;
    const float* wk = W + k * 1024;
    float s00 = 1.f, s01 = 1.f, s10 = 1.f, s11 = 1.f;
    if (which) {
        s00 = g_coef1[cin0];     s01 = g_coef1[cin0 + 1];
        s10 = g_coef1[cin0 + 8]; s11 = g_coef1[cin0 + 9];
    }
    uint2 v;
    v.x = h2pack(wk[cin0 * 32 + cout] * s00,       wk[(cin0 + 1) * 32 + cout] * s01);
    v.y = h2pack(wk[(cin0 + 8) * 32 + cout] * s10, wk[(cin0 + 9) * 32 + cout] * s11);
    g_Wf[which][k * 256 + st * 32 + lane] = v;
}

// ================== conv: 32 rows/warp, double-buffered cp.async gather ======
// A tile/warp: 32 rows x 16 words, chunk-XOR swizzle (invariant under +16 rows).
// WHICH==0: src x16, pad=zeros, no transform. WHICH==1: src raw h1, pad=-d,
// post-ldmatrix transform relu(h+d) with a1 folded into W2 fragments.
// BN stats accumulated block-locally then atomicAdd'ed into g_stat[WHICH].
template<int WHICH>
__global__ __launch_bounds__(256, 3) void conv_mma(const int* __restrict__ IDX)
{
    const __half* SRC  = WHICH ? g_h1h : g_x16;
    __half*       DST  = WHICH ? g_h2h : g_h1h;

    __shared__ uint32_t sA[2][8][512];           // 32 KB
    __shared__ float red[2][8][32];              //  2 KB

    const int tid   = threadIdx.x;
    const int warp  = tid >> 5;
    const int lane  = tid & 31;
    const int g     = lane >> 2;
    const int tig   = lane & 3;
    const int wrow  = warp * 32;
    const int base  = blockIdx.x * ROWS_PB;
    const int q4    = lane & 3;
    const int rsub8 = lane >> 2;                 // rows rsub8 + 8i, i=0..3

    const __half* PADp = (WHICH ? g_pad : g_zero) + q4 * 8;

    // d coefs for the fragment transform (WHICH==1 only)
    __half2 dd[2][2];
    if (WHICH) {
#pragma unroll
        for (int s = 0; s < 2; s++)
#pragma unroll
            for (int p = 0; p < 2; p++) {
                int cin = 16 * s + 8 * p + 2 * tig;
                float a0 = g_coef1[cin],      a1 = g_coef1[cin + 1];
                float c0 = g_coef1[32 + cin], c1 = g_coef1[32 + cin + 1];
                dd[s][p] = __floats2half2_rn(c0 / a0, c1 / a1);
            }
    }

    float acc[8][4];                             // [h*4+t][i]
#pragma unroll
    for (int t = 0; t < 8; t++)
#pragma unroll
        for (int i = 0; i < 4; i++) acc[t][i] = 0.f;

    const int rowc = min(base + wrow + lane, N_ACT - 1);

    // ldmatrix per-thread word offsets (rows 0-15; +256 words for rows 16-31)
    const int mat = lane >> 3;
    const int rr  = (lane & 7) + ((mat & 1) << 3);
    const int swz = (rr >> 1) & 3;
    const uint32_t w_s0 = rr * 16 + (((mat >> 1)       ^ swz) << 2);
    const uint32_t w_s1 = rr * 16 + (((2 + (mat >> 1)) ^ swz) << 2);
    const uint32_t ub[2] = { smem_u32(&sA[0][warp][0]), smem_u32(&sA[1][warp][0]) };

#define LOADA(MYJ, BUF)                                                     \
    {                                                                       \
        _Pragma("unroll")                                                   \
        for (int i = 0; i < 4; i++) {                                       \
            int j = __shfl_sync(0xffffffffu, (MYJ), rsub8 + 8 * i);         \
            const __half* src = (j < N_ACT)                                 \
                ? SRC + (size_t)j * 32 + q4 * 8 : PADp;                     \
            int r = rsub8 + 8 * i;                                          \
            uint32_t dst = (BUF) + (r * 16 + ((q4 ^ ((r >> 1) & 3)) << 2)) * 4; \
            asm volatile("cp.async.cg.shared.global [%0], [%1], 16;"        \
                         :: "r"(dst), "l"(src));                            \
        }                                                                   \
        asm volatile("cp.async.commit_group;");                             \
    }
#define COMPK(BUF, K)                                                       \
    {                                                                       \
        _Pragma("unroll")                                                   \
        for (int s = 0; s < 2; s++) {                                       \
            const uint2* wp = &g_Wf[WHICH][(K) * 256 + s * 128 + lane];     \
            uint2 w0 = wp[0], w1 = wp[32], w2 = wp[64], w3 = wp[96];        \
            _Pragma("unroll")                                               \
            for (int h = 0; h < 2; h++) {                                   \
                uint32_t afr[4];                                            \
                ldmx4(afr, (BUF) + h * 1024 + (s ? w_s1 : w_s0) * 4);       \
                if (WHICH) {                                                \
                    afr[0] = addrelu_u32(afr[0], dd[s][0]);                 \
                    afr[1] = addrelu_u32(afr[1], dd[s][0]);                 \
                    afr[2] = addrelu_u32(afr[2], dd[s][1]);                 \
                    afr[3] = addrelu_u32(afr[3], dd[s][1]);                 \
                }                                                           \
                mma_f16(acc[h * 4 + 0], afr, w0);                           \
                mma_f16(acc[h * 4 + 1], afr, w1);                           \
                mma_f16(acc[h * 4 + 2], afr, w2);                           \
                mma_f16(acc[h * 4 + 3], afr, w3);                           \
            }                                                               \
        }                                                                   \
    }

    // prologue: k=0 gather in flight
    int myj_cur = IDX[rowc];
    LOADA(myj_cur, ub[0]);
    int myj_nxt = IDX[(size_t)N_ACT + rowc];

#pragma unroll 1
    for (int k = 0; k < 8; k++) {
        if (k < 7) {
            int myj = myj_nxt;
            if (k < 6) myj_nxt = IDX[(size_t)(k + 2) * N_ACT + rowc];
            LOADA(myj, ub[(k + 1) & 1]);
            asm volatile("cp.async.wait_group 1;");
        } else {
            asm volatile("cp.async.wait_group 0;");
        }
        __syncwarp();
        COMPK(ub[k & 1], k);
    }
#undef LOADA
#undef COMPK

    // ---- epilogue: fp16 H store + fp32 BN partials ----
    float s0[4], s1[4], q0[4], q1[4];
#pragma unroll
    for (int t = 0; t < 4; t++) { s0[t] = s1[t] = q0[t] = q1[t] = 0.f; }
#pragma unroll
    for (int h = 0; h < 2; h++) {
        const int r0 = base + wrow + 16 * h + g, r1 = r0 + 8;
        const bool v0 = r0 < N_ACT, v1 = r1 < N_ACT;
#pragma unroll
        for (int t = 0; t < 4; t++) {
            float c0 = acc[h*4+t][0], c1 = acc[h*4+t][1];
            float c2 = acc[h*4+t][2], c3 = acc[h*4+t][3];
            int col = t * 8 + tig * 2;
            if (v0) *(__half2*)(DST + (size_t)r0 * 32 + col) = __floats2half2_rn(c0, c1);
            if (v1) *(__half2*)(DST + (size_t)r1 * 32 + col) = __floats2half2_rn(c2, c3);
            s0[t] += (v0 ? c0 : 0.f) + (v1 ? c2 : 0.f);
            q0[t] += (v0 ? c0 * c0 : 0.f) + (v1 ? c2 * c2 : 0.f);
            s1[t] += (v0 ? c1 : 0.f) + (v1 ? c3 : 0.f);
            q1[t] += (v0 ? c1 * c1 : 0.f) + (v1 ? c3 * c3 : 0.f);
        }
    }
#pragma unroll
    for (int off = 4; off <= 16; off <<= 1) {
#pragma unroll
        for (int t = 0; t < 4; t++) {
            s0[t] += __shfl_xor_sync(0xffffffffu, s0[t], off);
            q0[t] += __shfl_xor_sync(0xffffffffu, q0[t], off);
            s1[t] += __shfl_xor_sync(0xffffffffu, s1[t], off);
            q1[t] += __shfl_xor_sync(0xffffffffu, q1[t], off);
        }
    }
    if (lane < 4) {
#pragma unroll
        for (int t = 0; t < 4; t++) {
            red[0][warp][t * 8 + lane * 2]     = s0[t];
            red[0][warp][t * 8 + lane * 2 + 1] = s1[t];
            red[1][warp][t * 8 + lane * 2]     = q0[t];
            red[1][warp][t * 8 + lane * 2 + 1] = q1[t];
        }
    }
    __syncthreads();
    if (warp == 0) {
        float ts = 0.f, tq = 0.f;
#pragma unroll
        for (int w = 0; w < 8; w++) { ts += red[0][w][lane]; tq += red[1][w][lane]; }
        atomicAdd(&g_stat[WHICH][lane],      ts);
        atomicAdd(&g_stat[WHICH][32 + lane], tq);
    }
}

// ---- coef: 1 block x 32 threads; which==0 also writes the conv2 pad row ----
__global__ void coef_kernel(const float* __restrict__ gamma,
                            const float* __restrict__ beta, int which)
{
    float* coef = which ? g_coef2 : g_coef1;
    int c = threadIdx.x;
    float mean = g_stat[which][c] / (float)N_ACT;
    float var  = fmaxf(g_stat[which][32 + c] / (float)N_ACT - mean * mean, 0.f);
    float a    = gamma[c] * rsqrtf(var + BN_EPS);
    float cc   = beta[c] - mean * a;
    coef[c]      = a;
    coef[32 + c] = cc;
    if (which == 0) g_pad[c] = __float2half(-cc / a);   // relu(pad+d) == 0
}

// ------------- bn2 + residual add -> out (8 halfs per thread) -------------
__global__ void final_kernel(const float* __restrict__ X, float* __restrict__ O)
{
    size_t i8 = (size_t)blockIdx.x * 256 + threadIdx.x;
    if (i8 >= (size_t)N_ACT * 32 / 8) return;
    int cb = (int)(i8 & 3);                     // channel base = cb*8
    float4 a0 = ((const float4*)g_coef2)[cb * 2];
    float4 a1 = ((const float4*)g_coef2)[cb * 2 + 1];
    float4 c0 = ((const float4*)g_coef2)[8 + cb * 2];
    float4 c1 = ((const float4*)g_coef2)[8 + cb * 2 + 1];
    uint4 hv = ((const uint4*)g_h2h)[i8];
    float2 v0 = __half22float2(*(__half2*)&hv.x);
    float2 v1 = __half22float2(*(__half2*)&hv.y);
    float2 v2 = __half22float2(*(__half2*)&hv.z);
    float2 v3 = __half22float2(*(__half2*)&hv.w);
    float4 x0 = ((const float4*)X)[2 * i8], x1 = ((const float4*)X)[2 * i8 + 1];
    float4 o0, o1;
    o0.x = fmaf(v0.x, a0.x, c0.x) + x0.x;
    o0.y = fmaf(v0.y, a0.y, c0.y) + x0.y;
    o0.z = fmaf(v1.x, a0.z, c0.z) + x0.z;
    o0.w = fmaf(v1.y, a0.w, c0.w) + x0.w;
    o1.x = fmaf(v2.x, a1.x, c1.x) + x1.x;
    o1.y = fmaf(v2.y, a1.y, c1.y) + x1.y;
    o1.z = fmaf(v3.x, a1.z, c1.z) + x1.z;
    o1.w = fmaf(v3.y, a1.w, c1.w) + x1.w;
    ((float4*)O)[2 * i8]     = o0;
    ((float4*)O)[2 * i8 + 1] = o1;
}

extern "C" void kernel_launch(void* const* d_in, const int* in_sizes, int n_in,
                              void* d_out, int out_size)
{
    const float* x   = (const float*)d_in[0];
    const int*   idx = (const int*)  d_in[1];
    const float* W1  = (const float*)d_in[2];
    const float* g1  = (const float*)d_in[3];
    const float* b1  = (const float*)d_in[4];
    const float* W2  = (const float*)d_in[5];
    const float* g2  = (const float*)d_in[6];
    const float* b2  = (const float*)d_in[7];
    float* out = (float*)d_out;

    x_to_h <<<NB_CVT, 256>>>(x);              // x16 = fp16(x)
    prep_w <<<8, 256>>>(W1, 0);               // W1 frags + zero stat[0]
    conv_mma<0><<<NBC, 256>>>(idx);           // h1 = conv1(x16), stats -> atomic
    coef_kernel<<<1, 32>>>(g1, b1, 0);        // coef1 + pad row
    prep_w <<<8, 256>>>(W2, 1);               // W2' = a1-scaled frags + zero stat[1]
    conv_mma<1><<<NBC, 256>>>(idx);           // h2 = conv2(relu(h1+d))*a1-fold
    coef_kernel<<<1, 32>>>(g2, b2, 1);        // coef2
    final_kernel<<<NB_FIN, 256>>>(x, out);    // out = bn2(h2) + x
}